// round 2
// baseline (speedup 1.0000x reference)
#include <cuda_runtime.h>
#include <cuda_bf16.h>
#include <cstdint>

#define NNODES 100000
#define INF 64
#define OUTF 64

// Scratch: __device__ globals (runtime allocation is forbidden).
// g_msg4 as float4 guarantees 16B alignment for red.global.add.v4.f32.
__device__ float4 g_msg4[(size_t)NNODES * (INF / 4)];   // 25.6 MB, viewed as [N][64] floats
__device__ float  g_deg[NNODES];

// ---------------------------------------------------------------------------
// Kernel 1: zero the scratch (msg sums + degree)
// ---------------------------------------------------------------------------
__global__ void zero_kernel() {
    int i = blockIdx.x * blockDim.x + threadIdx.x;
    int total4 = NNODES * (INF / 4);
    if (i < total4) g_msg4[i] = make_float4(0.f, 0.f, 0.f, 0.f);
    if (i < NNODES) g_deg[i] = 0.f;
}

// ---------------------------------------------------------------------------
// Kernel 2: edge scatter.  thread t -> edge e = t/16, float4-chunk c = t%16.
// Consecutive threads cover one 64-float row -> coalesced L2-resident gather
// of h[src] and coalesced vector reduction atomics into g_msg[dst].
// Lane c==0 additionally bumps the degree counter.
// NOTE: src/dst are int32 (JAX default x64-disabled downgrades int64->int32).
// ---------------------------------------------------------------------------
__global__ void scatter_kernel(const float* __restrict__ h,
                               const int* __restrict__ src,
                               const int* __restrict__ dst,
                               int E) {
    long long t = (long long)blockIdx.x * blockDim.x + threadIdx.x;
    if (t >= (long long)E * 16) return;
    int e = (int)(t >> 4);
    int c = (int)(t & 15);
    int s = src[e];
    int d = dst[e];

    float4 v = ((const float4*)(h + (long long)s * INF))[c];
    float* p = ((float*)g_msg4) + (long long)d * INF + c * 4;
    asm volatile("red.global.add.v4.f32 [%0], {%1,%2,%3,%4};"
                 :: "l"(p), "f"(v.x), "f"(v.y), "f"(v.z), "f"(v.w)
                 : "memory");
    if (c == 0) atomicAdd(&g_deg[d], 1.0f);
}

// ---------------------------------------------------------------------------
// Kernel 3: per-node mean + fused concat-GEMM + bias + ReLU.
// Block = 256 threads handles 4 nodes.  W^T is staged in smem padded to 65
// floats/row (conflict-free both on the transposing store and on the compute
// read where 64 threads of one node read consecutive o).
// out[n][o] = relu( b[o] + sum_k h[n][k]*W[o][k] + sum_k hn[n][k]*W[o][64+k] )
// ---------------------------------------------------------------------------
__global__ void out_kernel(const float* __restrict__ h,
                           const float* __restrict__ W,   // [64][128] row-major
                           const float* __restrict__ b,
                           float* __restrict__ out) {
    __shared__ float Wt[128 * 65];       // Wt[k*65 + o] = W[o*128 + k]
    __shared__ float hbuf[4][INF];
    __shared__ float nbuf[4][INF];

    int tid = threadIdx.x;
    for (int i = tid; i < OUTF * 2 * INF; i += 256) {
        int o = i >> 7;        // /128
        int k = i & 127;
        Wt[k * 65 + o] = W[i];
    }

    int n_l = tid >> 6;        // 0..3
    int k   = tid & 63;        // 0..63
    int n   = blockIdx.x * 4 + n_l;   // N=100000 divisible by 4 -> always valid

    hbuf[n_l][k] = h[(long long)n * INF + k];
    float dg  = g_deg[n];
    float inv = 1.0f / fmaxf(dg, 1.0f);
    nbuf[n_l][k] = ((const float*)g_msg4)[(long long)n * INF + k] * inv;
    __syncthreads();

    int o = k;
    float acc = b[o];
#pragma unroll
    for (int kk = 0; kk < INF; kk++)
        acc += hbuf[n_l][kk] * Wt[kk * 65 + o];
#pragma unroll
    for (int kk = 0; kk < INF; kk++)
        acc += nbuf[n_l][kk] * Wt[(INF + kk) * 65 + o];

    out[(long long)n * OUTF + o] = fmaxf(acc, 0.0f);
}

// ---------------------------------------------------------------------------
// inputs (metadata order): h [N,64] f32, src [E] i32, dst [E] i32,
//                          W [64,128] f32, b [64] f32
// output: [N,64] f32
// ---------------------------------------------------------------------------
extern "C" void kernel_launch(void* const* d_in, const int* in_sizes, int n_in,
                              void* d_out, int out_size) {
    const float* h   = (const float*)d_in[0];
    const int*   src = (const int*)d_in[1];
    const int*   dst = (const int*)d_in[2];
    const float* W   = (const float*)d_in[3];
    const float* b   = (const float*)d_in[4];
    float*       out = (float*)d_out;

    int E = in_sizes[1];

    // zero scratch
    {
        int total = NNODES * (INF / 4);   // 1.6M float4 stores; deg piggybacks
        int blocks = (total + 255) / 256;
        zero_kernel<<<blocks, 256>>>();
    }
    // scatter
    {
        long long threads = (long long)E * 16;
        int blocks = (int)((threads + 255) / 256);
        scatter_kernel<<<blocks, 256>>>(h, src, dst, E);
    }
    // mean + GEMM + relu
    {
        int blocks = NNODES / 4;
        out_kernel<<<blocks, 256>>>(h, W, b, out);
    }
}

// round 3
// speedup vs baseline: 1.9062x; 1.9062x over previous
#include <cuda_runtime.h>
#include <cuda_bf16.h>
#include <cstdint>

#define NNODES 100000
#define INF 64
#define OUTF 64

typedef unsigned long long ull;

// Scratch (__device__ globals; runtime allocation forbidden).
__device__ float4 g_msg4[(size_t)NNODES * (INF / 4)];   // 25.6 MB [N][64]
__device__ float  g_deg[NNODES];

// ---------------------------------------------------------------------------
// Kernel 1: zero scratch
// ---------------------------------------------------------------------------
__global__ void zero_kernel() {
    int i = blockIdx.x * blockDim.x + threadIdx.x;
    int total4 = NNODES * (INF / 4);
    if (i < total4) g_msg4[i] = make_float4(0.f, 0.f, 0.f, 0.f);
    if (i < NNODES) g_deg[i] = 0.f;
}

// ---------------------------------------------------------------------------
// Kernel 2: edge scatter (unchanged from R2 — clean attribution).
// thread t -> edge e = t/16, float4-chunk c = t%16.
// ---------------------------------------------------------------------------
__global__ void scatter_kernel(const float* __restrict__ h,
                               const int* __restrict__ src,
                               const int* __restrict__ dst,
                               int E) {
    long long t = (long long)blockIdx.x * blockDim.x + threadIdx.x;
    if (t >= (long long)E * 16) return;
    int e = (int)(t >> 4);
    int c = (int)(t & 15);
    int s = src[e];
    int d = dst[e];

    float4 v = ((const float4*)(h + (long long)s * INF))[c];
    float* p = ((float*)g_msg4) + (long long)d * INF + c * 4;
    asm volatile("red.global.add.v4.f32 [%0], {%1,%2,%3,%4};"
                 :: "l"(p), "f"(v.x), "f"(v.y), "f"(v.z), "f"(v.w)
                 : "memory");
    if (c == 0) atomicAdd(&g_deg[d], 1.0f);
}

// ---------------------------------------------------------------------------
// f32x2 packed-FMA helpers (sm_100 packed fp32 pipe; 2 FMAs per instruction)
// ---------------------------------------------------------------------------
__device__ __forceinline__ void fma2(ull& d, ull a, ull b) {
    asm("fma.rn.f32x2 %0, %1, %2, %0;" : "+l"(d) : "l"(a), "l"(b));
}
__device__ __forceinline__ ull dup2(float x) {
    ull r; asm("mov.b64 %0, {%1, %2};" : "=l"(r) : "f"(x), "f"(x)); return r;
}
__device__ __forceinline__ void unpack2(ull v, float& x, float& y) {
    asm("mov.b64 {%0, %1}, %2;" : "=f"(x), "=f"(y) : "l"(v));
}

// ---------------------------------------------------------------------------
// Kernel 3: register-tiled mean+concat-GEMM+bias+ReLU.
// Block: 64 nodes x 64 outs, 128 threads; thread tile 8 nodes x 4 outs.
// K processed in two 64-halves: half0 = h, half1 = msg/deg.
// As[k][n] (stride 68) -> node pairs read as packed ulonglong2 for f32x2 FMA.
// Ws[k][o] (stride 68) -> float4 per (kk, o0), duplicated into pairs.
// ---------------------------------------------------------------------------
__global__ __launch_bounds__(128)
void out_kernel(const float* __restrict__ h,
                const float* __restrict__ W,   // [64][128] row-major
                const float* __restrict__ b,
                float* __restrict__ out) {
    __shared__ float As[64 * 68];
    __shared__ float Ws[64 * 68];
    __shared__ float invDeg[64];

    int tid = threadIdx.x;
    int tn = tid & 7;         // node-group 0..7
    int to = tid >> 3;        // out-group  0..15
    int n0 = tn * 8;
    int o0 = to * 4;
    int gn = blockIdx.x * 64;

    if (tid < 64) {
        int n = gn + tid;
        float dg = (n < NNODES) ? g_deg[n] : 1.0f;
        invDeg[tid] = 1.0f / fmaxf(dg, 1.0f);
    }

    ull acc[4][4];
#pragma unroll
    for (int j = 0; j < 4; j++)
#pragma unroll
        for (int oi = 0; oi < 4; oi++) acc[j][oi] = 0ULL;

#pragma unroll 1
    for (int half = 0; half < 2; half++) {
        __syncthreads();   // also covers invDeg for half 1, and As/Ws reuse
        // stage A-half transposed: As[k*68 + n]
        for (int i = tid; i < 64 * 64; i += 128) {
            int n = i >> 6, k = i & 63;
            int ng = gn + n;
            float v = 0.0f;
            if (ng < NNODES) {
                v = (half == 0)
                    ? h[(size_t)ng * INF + k]
                    : ((const float*)g_msg4)[(size_t)ng * INF + k] * invDeg[n];
            }
            As[k * 68 + n] = v;
        }
        // stage W-half transposed: Ws[k*68 + o] = W[o*128 + half*64 + k]
        for (int i = tid; i < 64 * 64; i += 128) {
            int o = i >> 6, k = i & 63;
            Ws[k * 68 + o] = W[o * 128 + half * 64 + k];
        }
        __syncthreads();

#pragma unroll 8
        for (int kk = 0; kk < 64; kk++) {
            const float* arow = &As[kk * 68 + n0];
            ulonglong2 av0 = *(const ulonglong2*)(arow);      // nodes n0+0..3 (2 pairs)
            ulonglong2 av1 = *(const ulonglong2*)(arow + 4);  // nodes n0+4..7 (2 pairs)
            float4 wv = *(const float4*)&Ws[kk * 68 + o0];

            ull ap[4] = {av0.x, av0.y, av1.x, av1.y};
            ull wp[4] = {dup2(wv.x), dup2(wv.y), dup2(wv.z), dup2(wv.w)};
#pragma unroll
            for (int j = 0; j < 4; j++)
#pragma unroll
                for (int oi = 0; oi < 4; oi++)
                    fma2(acc[j][oi], ap[j], wp[oi]);
        }
    }

    // epilogue: unpack, +bias, relu, vectorized store
    float4 bv = *(const float4*)&b[o0];
    float bb[4] = {bv.x, bv.y, bv.z, bv.w};
#pragma unroll
    for (int j = 0; j < 4; j++) {
        float x0[4], x1[4];
#pragma unroll
        for (int oi = 0; oi < 4; oi++) unpack2(acc[j][oi], x0[oi], x1[oi]);
        int n = gn + n0 + 2 * j;
        if (n < NNODES) {
            float4 r;
            r.x = fmaxf(x0[0] + bb[0], 0.0f);
            r.y = fmaxf(x0[1] + bb[1], 0.0f);
            r.z = fmaxf(x0[2] + bb[2], 0.0f);
            r.w = fmaxf(x0[3] + bb[3], 0.0f);
            *(float4*)&out[(size_t)n * OUTF + o0] = r;
        }
        if (n + 1 < NNODES) {
            float4 r;
            r.x = fmaxf(x1[0] + bb[0], 0.0f);
            r.y = fmaxf(x1[1] + bb[1], 0.0f);
            r.z = fmaxf(x1[2] + bb[2], 0.0f);
            r.w = fmaxf(x1[3] + bb[3], 0.0f);
            *(float4*)&out[(size_t)(n + 1) * OUTF + o0] = r;
        }
    }
}

// ---------------------------------------------------------------------------
// inputs: h [N,64] f32, src [E] i32, dst [E] i32, W [64,128] f32, b [64] f32
// output: [N,64] f32
// ---------------------------------------------------------------------------
extern "C" void kernel_launch(void* const* d_in, const int* in_sizes, int n_in,
                              void* d_out, int out_size) {
    const float* h   = (const float*)d_in[0];
    const int*   src = (const int*)d_in[1];
    const int*   dst = (const int*)d_in[2];
    const float* W   = (const float*)d_in[3];
    const float* b   = (const float*)d_in[4];
    float*       out = (float*)d_out;

    int E = in_sizes[1];

    {
        int total = NNODES * (INF / 4);
        zero_kernel<<<(total + 255) / 256, 256>>>();
    }
    {
        long long threads = (long long)E * 16;
        int blocks = (int)((threads + 255) / 256);
        scatter_kernel<<<blocks, 256>>>(h, src, dst, E);
    }
    {
        int blocks = (NNODES + 63) / 64;   // 1563
        out_kernel<<<blocks, 128>>>(h, W, b, out);
    }
}